// round 6
// baseline (speedup 1.0000x reference)
#include <cuda_runtime.h>
#include <math_constants.h>

#define TT 50
#define TR 48
#define SSTART 48
#define SSTOP 49
#define LL 512
#define BB 1024
#define NTH 64

__device__ __forceinline__ unsigned long long pack2f(float a, float b) {
    unsigned long long u;
    asm("mov.b64 %0, {%1, %2};" : "=l"(u) : "f"(a), "f"(b));
    return u;
}
__device__ __forceinline__ void unpack2f(unsigned long long u, float& a, float& b) {
    asm("mov.b64 {%0, %1}, %2;" : "=f"(a), "=f"(b) : "l"(u));
}
// d = a*b + d, packed 2xf32 (Blackwell FFMA2)
__device__ __forceinline__ void fma2(unsigned long long& d,
                                     unsigned long long a, unsigned long long b) {
    asm("fma.rn.f32x2 %0, %1, %2, %0;" : "+l"(d) : "l"(a), "l"(b));
}
__device__ __forceinline__ float frcp(float x) {
    float r;
    asm("rcp.approx.f32 %0, %1;" : "=f"(r) : "f"(x));
    return r;
}

__global__ void zero_out_k(float* o) {
    if (threadIdx.x == 0) o[0] = 0.0f;
}

__global__ __launch_bounds__(NTH) void crf_nll_kernel(
    const float* __restrict__ logits,   // [B, L, T]
    const float* __restrict__ trans,    // [T, T]
    const int*   __restrict__ labels,   // [B, L]
    const int*   __restrict__ lens,     // [B]
    float* __restrict__ out)            // scalar
{
    const int b = blockIdx.x;
    const int j = threadIdx.x;

    __shared__ __align__(16) float w_s[2 * TR];   // double-buffered scaled alphas
    __shared__ int   lab_s[LL];
    __shared__ float score_s;
    __shared__ float sum_s[2];

    const int len = lens[b];
    const float* lrow  = logits + (long)b * (LL * TT);
    const int*  labrow = labels + (long)b * LL;

    unsigned long long M2[TR / 2];
    float w = 0.0f, C = 0.0f, eStop = 0.0f;
    float el = 0.0f, lgN = 0.0f;   // 3-stage logit pipeline: el=exp(lg_t), lgN=lg_{t+1}

    if (j < TR) {
        // ---- recursion lanes: M row (exp of transitions) + scaled alpha init.
        // START row / STOP column are -1e4 -> exp underflows to exactly 0,
        // matching the reference's logsumexp, so both degenerate states are
        // dropped from the 48-state recursion.
        const float* trow = trans + j * TT;
        #pragma unroll
        for (int i = 0; i < TR / 2; ++i)
            M2[i] = pack2f(__expf(trow[2 * i]), __expf(trow[2 * i + 1]));
        eStop = __expf(trans[SSTOP * TT + j]);
        // t = 0: w = exp(alpha0) = exp(logit0 + trans[j, START]), C = 0
        w = __expf(lrow[j] + trow[SSTART]);
        w_s[j] = w;
        // prime the pipeline: exp(logit t=1) and raw logit t=2
        el  = __expf((1 < len) ? lrow[TT + j] : 0.0f);
        lgN = (2 < len) ? lrow[2 * TT + j] : 0.0f;
    } else {
        // ---- scoring lanes (16): gold-path emission + transition score,
        // fully parallel, done once before the recursion.
        const int s = j - 48;
        for (int t = s; t < len; t += 16) lab_s[t] = labrow[t];   // coalesced
        __syncwarp(0xFFFF0000u);
        float em = 0.0f, tr = 0.0f;
        #pragma unroll 4
        for (int t = s; t < len; t += 16) {
            int lb = lab_s[t];
            em += lrow[t * TT + lb];
            if (t > 0) tr += trans[lb * TT + lab_s[t - 1]];
        }
        if (s == 0)
            tr += trans[lab_s[0] * TT + SSTART] + trans[SSTOP * TT + lab_s[len - 1]];
        float sc = em + tr;
        #pragma unroll
        for (int d = 8; d >= 1; d >>= 1)
            sc += __shfl_xor_sync(0xFFFF0000u, sc, d);
        if (s == 0) score_s = sc;
    }
    __syncthreads();

    // ---- scaled forward recursion: w' = e^{lg} * (M_j . w) * rcp(w[0]).
    // w[0] (low element of the first LDS.128 every thread already does) is a
    // block-uniform normalizer obtained for FREE — no reduction, no broadcast.
    // Logit LDG is issued TWO steps ahead of use so DRAM latency (~400-600cyc)
    // is fully covered by two matvec intervals.
    int p = 0;
    for (int t = 1; t < len; ++t) {
        // issue LDG for logit(t+2); consumed two iterations from now
        float lgF = (j < TR && (t + 2) < len) ? lrow[(t + 2) * TT + j] : 0.0f;

        if (j < TR) {
            const ulonglong2* vv = reinterpret_cast<const ulonglong2*>(w_s + p * TR);
            ulonglong2 q0 = vv[0];
            float w0, wdum;
            unpack2f(q0.x, w0, wdum);
            const float rn = frcp(w0);                    // MUFU, overlapped
            unsigned long long a0 = 0, a1 = 0, a2 = 0, a3 = 0;
            ulonglong2 q1 = vv[1];
            fma2(a0, M2[0], q0.x);
            fma2(a1, M2[1], q0.y);
            fma2(a2, M2[2], q1.x);
            fma2(a3, M2[3], q1.y);
            #pragma unroll
            for (int i = 1; i < TR / 8; ++i) {
                ulonglong2 r0 = vv[2 * i];
                ulonglong2 r1 = vv[2 * i + 1];
                fma2(a0, M2[4 * i + 0], r0.x);
                fma2(a1, M2[4 * i + 1], r0.y);
                fma2(a2, M2[4 * i + 2], r1.x);
                fma2(a3, M2[4 * i + 3], r1.y);
            }
            float f0, f1, f2, f3, f4, f5, f6, f7;
            unpack2f(a0, f0, f1); unpack2f(a1, f2, f3);
            unpack2f(a2, f4, f5); unpack2f(a3, f6, f7);
            const float S = ((f0 + f1) + (f2 + f3)) + ((f4 + f5) + (f6 + f7));

            w = el * S * rn;                 // critical path tail
            w_s[(p ^ 1) * TR + j] = w;
            C += __logf(w0);                 // off-path scale bookkeeping
            el = __expf(lgN);                // off-path: exp(logit t+1)
            lgN = lgF;                       // shift pipeline
        }
        __syncthreads();
        p ^= 1;
    }

    // ---- partition = C + log( sum_j w_j * exp(trans[STOP, j]) )
    float f = (j < TR) ? w * eStop : 0.0f;
    #pragma unroll
    for (int d = 16; d >= 1; d >>= 1)
        f += __shfl_xor_sync(0xFFFFFFFFu, f, d);
    if ((j & 31) == 0) sum_s[j >> 5] = f;
    __syncthreads();

    if (j == 0) {
        float part = C + __logf(sum_s[0] + sum_s[1]);
        atomicAdd(out, (part - score_s) * (1.0f / (float)BB));
    }
}

extern "C" void kernel_launch(void* const* d_in, const int* in_sizes, int n_in,
                              void* d_out, int out_size) {
    const float* logits = (const float*)d_in[0];
    const float* trans  = (const float*)d_in[1];
    const int*   labels = (const int*)d_in[2];
    const int*   lens   = (const int*)d_in[3];
    float* out = (float*)d_out;

    zero_out_k<<<1, 32>>>(out);
    crf_nll_kernel<<<BB, NTH>>>(logits, trans, labels, lens, out);
}

// round 7
// speedup vs baseline: 1.3341x; 1.3341x over previous
#include <cuda_runtime.h>
#include <math_constants.h>

#define TT 50
#define TR 48
#define SSTART 48
#define SSTOP 49
#define LL 512
#define BB 1024
#define NTH 64
#define GRID 740   // 5 CTAs/SM * 148 SMs, persistent

__device__ int g_order[BB];
__device__ int g_counter;

__device__ __forceinline__ unsigned long long pack2f(float a, float b) {
    unsigned long long u;
    asm("mov.b64 %0, {%1, %2};" : "=l"(u) : "f"(a), "f"(b));
    return u;
}
__device__ __forceinline__ void unpack2f(unsigned long long u, float& a, float& b) {
    asm("mov.b64 {%0, %1}, %2;" : "=f"(a), "=f"(b) : "l"(u));
}
// d = a*b + d, packed 2xf32 (Blackwell FFMA2)
__device__ __forceinline__ void fma2(unsigned long long& d,
                                     unsigned long long a, unsigned long long b) {
    asm("fma.rn.f32x2 %0, %1, %2, %0;" : "+l"(d) : "l"(a), "l"(b));
}
__device__ __forceinline__ float frcp(float x) {
    float r;
    asm("rcp.approx.f32 %0, %1;" : "=f"(r) : "f"(x));
    return r;
}

// Counting sort of batch indices by DESCENDING length (LPT order) +
// reset work counter and output. One block, 1024 threads.
__global__ void setup_k(const int* __restrict__ lens, float* out) {
    __shared__ int hist[LL + 1];
    const int t = threadIdx.x;
    if (t <= LL) hist[t] = 0;
    if (t == 0) { g_counter = 0; out[0] = 0.0f; }
    __syncthreads();
    atomicAdd(&hist[lens[t]], 1);
    __syncthreads();
    if (t == 0) {                       // descending exclusive offsets
        int run = 0;
        for (int l = LL; l >= 1; --l) { int h = hist[l]; hist[l] = run; run += h; }
    }
    __syncthreads();
    int pos = atomicAdd(&hist[lens[t]], 1);
    g_order[pos] = t;
}

__global__ __launch_bounds__(NTH) void crf_nll_kernel(
    const float* __restrict__ logits,   // [B, L, T]
    const float* __restrict__ trans,    // [T, T]
    const int*   __restrict__ labels,   // [B, L]
    const int*   __restrict__ lens,     // [B]
    float* __restrict__ out)            // scalar
{
    const int j = threadIdx.x;

    __shared__ __align__(16) float w_s[2 * TR];   // double-buffered scaled alphas
    __shared__ int   lab_s[LL];
    __shared__ float score_s;
    __shared__ float sum_s[2];
    __shared__ int   bidx_s;

    // Per-CTA constants (depend only on trans) — hoisted out of the work loop.
    unsigned long long M2[TR / 2];
    float eStop = 0.0f;
    if (j < TR) {
        // START row / STOP column are -1e4 -> exp underflows to exactly 0,
        // matching the reference's logsumexp, so both degenerate states are
        // dropped from the 48-state recursion.
        const float* trow = trans + j * TT;
        #pragma unroll
        for (int i = 0; i < TR / 2; ++i)
            M2[i] = pack2f(__expf(trow[2 * i]), __expf(trow[2 * i + 1]));
        eStop = __expf(trans[SSTOP * TT + j]);
    }

    // Persistent work loop: sequences fetched longest-first (LPT balance).
    for (;;) {
        if (j == 0) bidx_s = atomicAdd(&g_counter, 1);
        __syncthreads();
        const int i = bidx_s;
        if (i >= BB) break;
        const int b = g_order[i];

        const int len = lens[b];
        const float* lrow  = logits + (long)b * (LL * TT);
        const int*  labrow = labels + (long)b * LL;

        float w = 0.0f, C = 0.0f, el = 0.0f;

        if (j < TR) {
            // t = 0: w = exp(alpha0) = exp(logit0 + trans[j, START]), C = 0
            w = __expf(lrow[j] + trans[j * TT + SSTART]);
            w_s[j] = w;
            el = __expf((1 < len) ? lrow[TT + j] : 0.0f);   // prefetch t=1
        } else {
            // scoring lanes (16): gold-path emission + transition score
            const int s = j - 48;
            for (int t = s; t < len; t += 16) lab_s[t] = labrow[t];
            __syncwarp(0xFFFF0000u);
            float em = 0.0f, tr = 0.0f;
            #pragma unroll 4
            for (int t = s; t < len; t += 16) {
                int lb = lab_s[t];
                em += lrow[t * TT + lb];
                if (t > 0) tr += trans[lb * TT + lab_s[t - 1]];
            }
            if (s == 0)
                tr += trans[lab_s[0] * TT + SSTART] + trans[SSTOP * TT + lab_s[len - 1]];
            float sc = em + tr;
            #pragma unroll
            for (int d = 8; d >= 1; d >>= 1)
                sc += __shfl_xor_sync(0xFFFF0000u, sc, d);
            if (s == 0) score_s = sc;
        }
        __syncthreads();

        // scaled forward recursion: w' = e^{lg} * (M_j . w) * rcp(w[0]);
        // w[0] (low half of the first LDS.128) is a free block-uniform
        // normalizer; rcp overlaps the FFMA2 chain, log(w0) is off-path.
        int p = 0;
        for (int t = 1; t < len; ++t) {
            const int tn = (t + 1 < len) ? (t + 1) : t;        // clamped prefetch
            float lgN = (j < TR) ? lrow[tn * TT + j] : 0.0f;

            if (j < TR) {
                const ulonglong2* vv = reinterpret_cast<const ulonglong2*>(w_s + p * TR);
                ulonglong2 q0 = vv[0];
                float w0, wdum;
                unpack2f(q0.x, w0, wdum);
                const float rn = frcp(w0);                     // MUFU, overlapped
                unsigned long long a0 = 0, a1 = 0, a2 = 0, a3 = 0;
                ulonglong2 q1 = vv[1];
                fma2(a0, M2[0], q0.x);
                fma2(a1, M2[1], q0.y);
                fma2(a2, M2[2], q1.x);
                fma2(a3, M2[3], q1.y);
                #pragma unroll
                for (int k = 1; k < TR / 8; ++k) {
                    ulonglong2 r0 = vv[2 * k];
                    ulonglong2 r1 = vv[2 * k + 1];
                    fma2(a0, M2[4 * k + 0], r0.x);
                    fma2(a1, M2[4 * k + 1], r0.y);
                    fma2(a2, M2[4 * k + 2], r1.x);
                    fma2(a3, M2[4 * k + 3], r1.y);
                }
                float f0, f1, f2, f3, f4, f5, f6, f7;
                unpack2f(a0, f0, f1); unpack2f(a1, f2, f3);
                unpack2f(a2, f4, f5); unpack2f(a3, f6, f7);
                const float S = ((f0 + f1) + (f2 + f3)) + ((f4 + f5) + (f6 + f7));

                w = el * S * rn;                // critical path tail
                w_s[(p ^ 1) * TR + j] = w;
                C += __logf(w0);                // off-path scale bookkeeping
                el = __expf(lgN);               // off-path, for next step
            }
            __syncthreads();
            p ^= 1;
        }

        // partition = C + log( sum_j w_j * exp(trans[STOP, j]) )
        float f = (j < TR) ? w * eStop : 0.0f;
        #pragma unroll
        for (int d = 16; d >= 1; d >>= 1)
            f += __shfl_xor_sync(0xFFFFFFFFu, f, d);
        if ((j & 31) == 0) sum_s[j >> 5] = f;
        __syncthreads();

        if (j == 0) {
            float part = C + __logf(sum_s[0] + sum_s[1]);
            atomicAdd(out, (part - score_s) * (1.0f / (float)BB));
        }
        __syncthreads();   // protect smem reuse before next fetch
    }
}

extern "C" void kernel_launch(void* const* d_in, const int* in_sizes, int n_in,
                              void* d_out, int out_size) {
    const float* logits = (const float*)d_in[0];
    const float* trans  = (const float*)d_in[1];
    const int*   labels = (const int*)d_in[2];
    const int*   lens   = (const int*)d_in[3];
    float* out = (float*)d_out;

    setup_k<<<1, BB>>>(lens, out);
    crf_nll_kernel<<<GRID, NTH>>>(logits, trans, labels, lens, out);
}

// round 9
// speedup vs baseline: 1.6299x; 1.2218x over previous
#include <cuda_runtime.h>

#define TT 50
#define TR 48
#define SSTART 48
#define SSTOP 49
#define LL 512
#define BB 1024

__device__ __forceinline__ unsigned long long pack2f(float a, float b) {
    unsigned long long u;
    asm("mov.b64 %0, {%1, %2};" : "=l"(u) : "f"(a), "f"(b));
    return u;
}
__device__ __forceinline__ void unpack2f(unsigned long long u, float& a, float& b) {
    asm("mov.b64 {%0, %1}, %2;" : "=f"(a), "=f"(b) : "l"(u));
}
// d = a*b + d, packed 2xf32 (Blackwell FFMA2)
__device__ __forceinline__ void fma2(unsigned long long& d,
                                     unsigned long long a, unsigned long long b) {
    asm("fma.rn.f32x2 %0, %1, %2, %0;" : "+l"(d) : "l"(a), "l"(b));
}
__device__ __forceinline__ float frcp(float x) {
    float r;
    asm("rcp.approx.f32 %0, %1;" : "=f"(r) : "f"(x));
    return r;
}

__global__ void zero_out_k(float* o) {
    if (threadIdx.x == 0) o[0] = 0.0f;
}

// One WARP per sequence. Lane l (<24) owns states 2l and 2l+1.
// No __syncthreads anywhere: double-buffered smem w + one __syncwarp/step.
// All 1024 one-warp CTAs are resident simultaneously (reg limit ~14/SM),
// so the kernel makespan is bounded by max(len), not per-SM length sums.
__global__ __launch_bounds__(32) void crf_nll_kernel(
    const float* __restrict__ logits,   // [B, L, T]
    const float* __restrict__ trans,    // [T, T]
    const int*   __restrict__ labels,   // [B, L]
    const int*   __restrict__ lens,     // [B]
    float* __restrict__ out)            // scalar
{
    const int b = blockIdx.x;
    const int l = threadIdx.x;
    const int sA = (l < 24) ? 2 * l : 0;    // clamped for idle lanes 24-31

    __shared__ __align__(16) float w_s[2][TR];

    const int len = lens[b];
    const float* lrow  = logits + (long)b * (LL * TT);
    const int*  labrow = labels + (long)b * LL;

    // M rows (exp of transitions) for this lane's two states, packed f32x2.
    // START row / STOP column are -1e4 -> exp underflows to exactly 0,
    // matching the reference's logsumexp; both degenerate states drop out.
    unsigned long long MA[24], MB[24];
    const float* trA = trans + sA * TT;
    const float* trB = trA + TT;
    #pragma unroll
    for (int i = 0; i < 24; ++i) {
        MA[i] = pack2f(__expf(trA[2 * i]), __expf(trA[2 * i + 1]));
        MB[i] = pack2f(__expf(trB[2 * i]), __expf(trB[2 * i + 1]));
    }
    const float eStopA = __expf(trans[SSTOP * TT + sA]);
    const float eStopB = __expf(trans[SSTOP * TT + sA + 1]);

    // ---- gold-path score: all 32 lanes, strided over t, L1-cached gathers
    float em = 0.0f, tr = 0.0f;
    for (int t = l; t < len; t += 32) {
        int lb = labrow[t];
        em += lrow[t * TT + lb];
        if (t > 0) tr += trans[lb * TT + labrow[t - 1]];
    }
    if (l == 0)
        tr += trans[labrow[0] * TT + SSTART] + trans[SSTOP * TT + labrow[len - 1]];
    float sc = em + tr;
    #pragma unroll
    for (int d = 16; d >= 1; d >>= 1)
        sc += __shfl_xor_sync(0xFFFFFFFFu, sc, d);

    // ---- init t = 0: w = exp(logit0 + trans[., START])
    float wA = __expf(lrow[sA]     + trA[SSTART]);
    float wB = __expf(lrow[sA + 1] + trB[SSTART]);
    if (l < 24)
        *reinterpret_cast<float2*>(&w_s[0][2 * l]) = make_float2(wA, wB);
    // prime logit pipeline for t = 1 (both states in one LDG.64; sA is even)
    float elA, elB;
    {
        float2 lg = (1 < len) ? *reinterpret_cast<const float2*>(lrow + TT + sA)
                              : make_float2(0.0f, 0.0f);
        elA = __expf(lg.x);
        elB = __expf(lg.y);
    }
    float C = 0.0f;
    __syncwarp();

    // ---- scaled forward recursion: w' = e^{lg} * (M . w) * rcp(w[0]).
    // w[0] (low half of the first LDS.128) is a free warp-uniform normalizer.
    int p = 0;
    for (int t = 1; t < len; ++t) {
        const int tn = (t + 1 < len) ? (t + 1) : t;              // clamped prefetch
        const float2 lgN = *reinterpret_cast<const float2*>(lrow + tn * TT + sA);

        const ulonglong2* vv = reinterpret_cast<const ulonglong2*>(w_s[p]);
        ulonglong2 q0 = vv[0];
        float w0, wd;
        unpack2f(q0.x, w0, wd);
        const float rn = frcp(w0);                                // MUFU, overlapped
        unsigned long long a0 = 0, a1 = 0, c0 = 0, c1 = 0;
        ulonglong2 q1 = vv[1];
        fma2(a0, MA[0], q0.x); fma2(a1, MA[1], q0.y);
        fma2(c0, MB[0], q0.x); fma2(c1, MB[1], q0.y);
        fma2(a0, MA[2], q1.x); fma2(a1, MA[3], q1.y);
        fma2(c0, MB[2], q1.x); fma2(c1, MB[3], q1.y);
        #pragma unroll
        for (int k = 1; k < 6; ++k) {
            ulonglong2 r0 = vv[2 * k];
            ulonglong2 r1 = vv[2 * k + 1];
            fma2(a0, MA[4 * k + 0], r0.x); fma2(a1, MA[4 * k + 1], r0.y);
            fma2(c0, MB[4 * k + 0], r0.x); fma2(c1, MB[4 * k + 1], r0.y);
            fma2(a0, MA[4 * k + 2], r1.x); fma2(a1, MA[4 * k + 3], r1.y);
            fma2(c0, MB[4 * k + 2], r1.x); fma2(c1, MB[4 * k + 3], r1.y);
        }
        float f0, f1, f2, f3, g0, g1, g2, g3;
        unpack2f(a0, f0, f1); unpack2f(a1, f2, f3);
        unpack2f(c0, g0, g1); unpack2f(c1, g2, g3);
        const float SA = (f0 + f1) + (f2 + f3);
        const float SB = (g0 + g1) + (g2 + g3);

        wA = elA * SA * rn;                 // critical path tail
        wB = elB * SB * rn;
        if (l < 24)
            *reinterpret_cast<float2*>(&w_s[p ^ 1][2 * l]) = make_float2(wA, wB);
        C += __logf(w0);                    // off-path scale bookkeeping
        elA = __expf(lgN.x);                // off-path, for next step
        elB = __expf(lgN.y);
        __syncwarp();
        p ^= 1;
    }

    // ---- partition = C + log( sum_j w_j * exp(trans[STOP, j]) )
    float f = (l < 24) ? (wA * eStopA + wB * eStopB) : 0.0f;
    #pragma unroll
    for (int d = 16; d >= 1; d >>= 1)
        f += __shfl_xor_sync(0xFFFFFFFFu, f, d);

    if (l == 0) {
        float part = C + __logf(f);
        atomicAdd(out, (part - sc) * (1.0f / (float)BB));
    }
}

extern "C" void kernel_launch(void* const* d_in, const int* in_sizes, int n_in,
                              void* d_out, int out_size) {
    const float* logits = (const float*)d_in[0];
    const float* trans  = (const float*)d_in[1];
    const int*   labels = (const int*)d_in[2];
    const int*   lens   = (const int*)d_in[3];
    float* out = (float*)d_out;

    zero_out_k<<<1, 32>>>(out);
    crf_nll_kernel<<<BB, 32>>>(logits, trans, labels, lens, out);
}